// round 1
// baseline (speedup 1.0000x reference)
#include <cuda_runtime.h>
#include <math.h>

#define SLEN 1024
#define BSZ  32
#define INDIM 512
#define NH   8
#define HD   64
#define NQKVB (NH * (3 * HD + 1))   // 1544
#define M_ROWS (SLEN * BSZ)         // 32768
#define LN_EPS 1e-5f

// -------- scratch (device globals: allocation-free, graph-safe) --------
__device__ float g_h[(size_t)M_ROWS * INDIM];     // 64 MB: LayerNorm output
__device__ float g_qkvb[(size_t)M_ROWS * NQKVB];  // 193 MB: slow-net projection
__device__ float g_o[(size_t)M_ROWS * INDIM];     // 64 MB: scan outputs

// ---------------------------------------------------------------------
__device__ __forceinline__ float warpsum(float v) {
    #pragma unroll
    for (int o = 16; o > 0; o >>= 1) v += __shfl_xor_sync(0xffffffffu, v, o);
    return v;
}

__device__ __forceinline__ float elu_p1(float x) {
    // elu(x)+1 = x+1 (x>0) else exp(x)
    return x > 0.0f ? x + 1.0f : __expf(x);
}

// ---------------- LayerNorm: one block per row of 512 ----------------
__global__ void __launch_bounds__(128) ln_kernel(const float* __restrict__ x,
                                                 const float* __restrict__ gamma,
                                                 const float* __restrict__ beta,
                                                 float* __restrict__ h) {
    const int row = blockIdx.x;
    const int tid = threadIdx.x;           // 0..127, 4 floats each
    const int lane = tid & 31, warp = tid >> 5;

    const float4 v = ((const float4*)(x + (size_t)row * INDIM))[tid];
    float s  = v.x + v.y + v.z + v.w;
    float s2 = v.x * v.x + v.y * v.y + v.z * v.z + v.w * v.w;
    s  = warpsum(s);
    s2 = warpsum(s2);

    __shared__ float ps[4], ps2[4];
    if (lane == 0) { ps[warp] = s; ps2[warp] = s2; }
    __syncthreads();
    s  = ps[0]  + ps[1]  + ps[2]  + ps[3];
    s2 = ps2[0] + ps2[1] + ps2[2] + ps2[3];

    const float mu   = s * (1.0f / INDIM);
    const float var  = s2 * (1.0f / INDIM) - mu * mu;
    const float rstd = rsqrtf(var + LN_EPS);

    const float4 g = ((const float4*)gamma)[tid];
    const float4 b = ((const float4*)beta)[tid];
    float4 o;
    o.x = (v.x - mu) * rstd * g.x + b.x;
    o.y = (v.y - mu) * rstd * g.y + b.y;
    o.z = (v.z - mu) * rstd * g.z + b.z;
    o.w = (v.w - mu) * rstd * g.w + b.w;
    ((float4*)(h + (size_t)row * INDIM))[tid] = o;
}

// ------------- fp32 SIMT GEMM: C[M,N] = A[M,K] @ B[K,N] --------------
// 64x64 tile, BK=16, 256 threads, 4x4 microtile. Optional fused residual.
template<bool ADD_RESID>
__global__ void __launch_bounds__(256) gemm_kernel(const float* __restrict__ A,
                                                   const float* __restrict__ B,
                                                   float* __restrict__ C,
                                                   const float* __restrict__ resid,
                                                   int M, int N, int K) {
    __shared__ float As[16][64];   // As[k][m] (A transposed in smem)
    __shared__ float Bs[16][64];   // Bs[k][n]

    const int tid = threadIdx.x;
    const int tx = tid & 15;       // 0..15 -> 4 cols each
    const int ty = tid >> 4;       // 0..15 -> 4 rows each
    const int m0 = blockIdx.y * 64;
    const int n0 = blockIdx.x * 64;

    // cooperative load mapping
    const int aRow = tid >> 2;          // 0..63
    const int aK   = (tid & 3) * 4;     // 0,4,8,12
    const int bK   = tid >> 4;          // 0..15
    const int bCol = (tid & 15) * 4;    // 0..60

    const float* Aptr = A + (size_t)(m0 + aRow) * K + aK;
    const float* Bptr = B + (size_t)bK * N + (n0 + bCol);
    const bool bValid = (n0 + bCol + 3) < N;   // N % 4 == 0, so float4 is all-or-nothing

    float c[4][4] = {};

    for (int k0 = 0; k0 < K; k0 += 16) {
        const float4 a4 = *(const float4*)(Aptr + k0);
        float4 b4 = make_float4(0.f, 0.f, 0.f, 0.f);
        if (bValid) b4 = *(const float4*)(Bptr + (size_t)k0 * N);

        As[aK + 0][aRow] = a4.x;
        As[aK + 1][aRow] = a4.y;
        As[aK + 2][aRow] = a4.z;
        As[aK + 3][aRow] = a4.w;
        *(float4*)&Bs[bK][bCol] = b4;
        __syncthreads();

        #pragma unroll
        for (int k = 0; k < 16; k++) {
            const float4 av = *(const float4*)&As[k][ty * 4];
            const float4 bv = *(const float4*)&Bs[k][tx * 4];
            c[0][0] += av.x * bv.x; c[0][1] += av.x * bv.y; c[0][2] += av.x * bv.z; c[0][3] += av.x * bv.w;
            c[1][0] += av.y * bv.x; c[1][1] += av.y * bv.y; c[1][2] += av.y * bv.z; c[1][3] += av.y * bv.w;
            c[2][0] += av.z * bv.x; c[2][1] += av.z * bv.y; c[2][2] += av.z * bv.z; c[2][3] += av.z * bv.w;
            c[3][0] += av.w * bv.x; c[3][1] += av.w * bv.y; c[3][2] += av.w * bv.z; c[3][3] += av.w * bv.w;
        }
        __syncthreads();
    }

    const int nOut = n0 + tx * 4;
    if (nOut + 3 < N) {
        #pragma unroll
        for (int r = 0; r < 4; r++) {
            const int m = m0 + ty * 4 + r;
            float4 o = make_float4(c[r][0], c[r][1], c[r][2], c[r][3]);
            if (ADD_RESID) {
                const float4 rv = *(const float4*)(resid + (size_t)m * N + nOut);
                o.x += rv.x; o.y += rv.y; o.z += rv.z; o.w += rv.w;
            }
            *(float4*)(C + (size_t)m * N + nOut) = o;
        }
    }
}

// --------------- delta-rule scan: one CTA per (b, h) -----------------
// 64 threads; thread i owns row i of the 64x64 state W in registers.
// Activations (elu+1, sum-norm as scalar factors, sigmoid) fused here.
// Double-buffered shared staging; global prefetch of step t+1 hidden
// under step-t compute.
__global__ void __launch_bounds__(64) scan_kernel(const float* __restrict__ qkvb,
                                                  float* __restrict__ o_out) {
    const int b   = blockIdx.x;   // 0..31
    const int h   = blockIdx.y;   // 0..7
    const int tid = threadIdx.x;  // 0..63
    const int lane = tid & 31, warp = tid >> 5;

    __shared__ float raws[2][200];          // [parity][q(64) k(64) v(64) beta(1)]
    __shared__ float qs[2][64], ks[2][64];  // unnormalized elu_p1 values
    __shared__ float red[2][2][2];          // [parity][q/k][warp] partial sums

    float W[HD];
    #pragma unroll
    for (int j = 0; j < HD; j++) W[j] = 0.0f;

    const float* base = qkvb + (size_t)b * NQKVB + (size_t)h * (3 * HD + 1);
    const size_t tstride = (size_t)BSZ * NQKVB;

    // prefetch t = 0
    float r0 = base[tid];
    float r1 = base[64 + tid];
    float r2 = base[128 + tid];
    float r3 = (tid == 0) ? base[192] : 0.0f;

    for (int t = 0; t < SLEN; t++) {
        const int par = t & 1;

        // stage raw step-t data
        raws[par][tid]       = r0;
        raws[par][64 + tid]  = r1;
        raws[par][128 + tid] = r2;
        if (tid == 0) raws[par][192] = r3;
        __syncthreads();

        // activations + per-warp partial sums
        const float eq = elu_p1(r0);
        const float ek = elu_p1(r1);
        qs[par][tid] = eq;
        ks[par][tid] = ek;
        const float sq = warpsum(eq);
        const float sk = warpsum(ek);
        if (lane == 0) { red[par][0][warp] = sq; red[par][1][warp] = sk; }
        const float beta = 1.0f / (1.0f + __expf(-raws[par][192]));
        const float v_i  = r2;

        // prefetch step t+1 (latency hidden by the compute below)
        if (t + 1 < SLEN) {
            const float* p = base + (size_t)(t + 1) * tstride;
            r0 = p[tid];
            r1 = p[64 + tid];
            r2 = p[128 + tid];
            if (tid == 0) r3 = p[192];
        }
        __syncthreads();

        const float invq = 1.0f / (red[par][0][0] + red[par][0][1]);
        const float invk = 1.0f / (red[par][1][0] + red[par][1][1]);

        // v_old_i = invk * dot(W_i, ks)
        float a0 = 0.f, a1 = 0.f, a2 = 0.f, a3 = 0.f;
        #pragma unroll
        for (int j = 0; j < HD; j += 4) {
            const float4 k4 = *(const float4*)&ks[par][j];
            a0 += W[j]     * k4.x;
            a1 += W[j + 1] * k4.y;
            a2 += W[j + 2] * k4.z;
            a3 += W[j + 3] * k4.w;
        }
        const float vold_raw = (a0 + a1) + (a2 + a3);
        // true update scalar folding both invk factors:
        // W_ij += [beta*(v_i - invk*vold_raw)] * (invk*ks_j)
        const float upd = beta * (v_i - invk * vold_raw) * invk;

        // rank-1 update + o_i = invq * dot(W_i_new, qs)
        float o0 = 0.f, o1 = 0.f, o2 = 0.f, o3 = 0.f;
        #pragma unroll
        for (int j = 0; j < HD; j += 4) {
            const float4 k4 = *(const float4*)&ks[par][j];
            const float4 q4 = *(const float4*)&qs[par][j];
            W[j]     += upd * k4.x;  o0 += W[j]     * q4.x;
            W[j + 1] += upd * k4.y;  o1 += W[j + 1] * q4.y;
            W[j + 2] += upd * k4.z;  o2 += W[j + 2] * q4.z;
            W[j + 3] += upd * k4.w;  o3 += W[j + 3] * q4.w;
        }
        const float o = ((o0 + o1) + (o2 + o3)) * invq;

        o_out[((size_t)t * BSZ + b) * (NH * HD) + h * HD + tid] = o;
        // no extra barrier: next iteration's stores hit the other parity,
        // and parity reuse is separated by the two barriers of step t+1.
    }
}

// ---------------------------------------------------------------------
extern "C" void kernel_launch(void* const* d_in, const int* in_sizes, int n_in,
                              void* d_out, int out_size) {
    const float* x      = (const float*)d_in[0];
    const float* gamma  = (const float*)d_in[1];
    const float* beta   = (const float*)d_in[2];
    const float* w_slow = (const float*)d_in[3];
    const float* w_out  = (const float*)d_in[4];
    float* out = (float*)d_out;

    float *hbuf, *qkvb, *obuf;
    cudaGetSymbolAddress((void**)&hbuf, g_h);
    cudaGetSymbolAddress((void**)&qkvb, g_qkvb);
    cudaGetSymbolAddress((void**)&obuf, g_o);

    // 1) LayerNorm
    ln_kernel<<<M_ROWS, 128>>>(x, gamma, beta, hbuf);

    // 2) qkvb = h @ w_slow   [32768,512] @ [512,1544]
    gemm_kernel<false><<<dim3((NQKVB + 63) / 64, M_ROWS / 64), 256>>>(
        hbuf, w_slow, qkvb, nullptr, M_ROWS, NQKVB, INDIM);

    // 3) delta-rule recurrence (activations fused)
    scan_kernel<<<dim3(BSZ, NH), 64>>>(qkvb, obuf);

    // 4) out = x + o @ w_out  [32768,512] @ [512,512]
    gemm_kernel<true><<<dim3(INDIM / 64, M_ROWS / 64), 256>>>(
        obuf, w_out, out, x, M_ROWS, INDIM, INDIM);
}

// round 3
// speedup vs baseline: 1.1472x; 1.1472x over previous
#include <cuda_runtime.h>
#include <math.h>

#define SLEN 1024
#define BSZ  32
#define INDIM 512
#define NH   8
#define HD   64
#define NQKVB (NH * (3 * HD + 1))   // 1544
#define M_ROWS (SLEN * BSZ)         // 32768
#define LN_EPS 1e-5f

// -------- scratch (device globals: allocation-free, graph-safe) --------
__device__ float g_h[(size_t)M_ROWS * INDIM];     // 64 MB: LayerNorm output
__device__ float g_qkvb[(size_t)M_ROWS * NQKVB];  // 193 MB: slow-net projection
__device__ float g_o[(size_t)M_ROWS * INDIM];     // 64 MB: scan outputs

// ---------------------------------------------------------------------
__device__ __forceinline__ float warpsum(float v) {
    #pragma unroll
    for (int o = 16; o > 0; o >>= 1) v += __shfl_xor_sync(0xffffffffu, v, o);
    return v;
}

__device__ __forceinline__ float elu_p1(float x) {
    return x > 0.0f ? x + 1.0f : __expf(x);
}

// ---------------- LayerNorm: one block per row of 512 ----------------
__global__ void __launch_bounds__(128) ln_kernel(const float* __restrict__ x,
                                                 const float* __restrict__ gamma,
                                                 const float* __restrict__ beta,
                                                 float* __restrict__ h) {
    const int row = blockIdx.x;
    const int tid = threadIdx.x;
    const int lane = tid & 31, warp = tid >> 5;

    const float4 v = ((const float4*)(x + (size_t)row * INDIM))[tid];
    float s  = v.x + v.y + v.z + v.w;
    float s2 = v.x * v.x + v.y * v.y + v.z * v.z + v.w * v.w;
    s  = warpsum(s);
    s2 = warpsum(s2);

    __shared__ float ps[4], ps2[4];
    if (lane == 0) { ps[warp] = s; ps2[warp] = s2; }
    __syncthreads();
    s  = ps[0]  + ps[1]  + ps[2]  + ps[3];
    s2 = ps2[0] + ps2[1] + ps2[2] + ps2[3];

    const float mu   = s * (1.0f / INDIM);
    const float var  = s2 * (1.0f / INDIM) - mu * mu;
    const float rstd = rsqrtf(var + LN_EPS);

    const float4 g = ((const float4*)gamma)[tid];
    const float4 b = ((const float4*)beta)[tid];
    float4 o;
    o.x = (v.x - mu) * rstd * g.x + b.x;
    o.y = (v.y - mu) * rstd * g.y + b.y;
    o.z = (v.z - mu) * rstd * g.z + b.z;
    o.w = (v.w - mu) * rstd * g.w + b.w;
    ((float4*)(h + (size_t)row * INDIM))[tid] = o;
}

// ------------- fp32 SIMT GEMM: C[M,N] = A[M,K] @ B[K,N] --------------
// 128x128 tile, BK=8, 256 threads, 8x8 microtile (split 4+4 for
// conflict-free LDS.128), double-buffered smem. 1 B LDS per FMA so the
// smem crossbar (128 B/cyc) no longer caps the fma pipe (128 FMA/cyc).
template<bool ADD_RESID>
__global__ void __launch_bounds__(256) sgemm128(const float* __restrict__ A,
                                                const float* __restrict__ B,
                                                float* __restrict__ C,
                                                const float* __restrict__ resid,
                                                int M, int N, int K) {
    __shared__ float As[2][8][128];   // As[buf][k][m]
    __shared__ float Bs[2][8][128];   // Bs[buf][k][n]

    const int tid = threadIdx.x;
    const int tx  = tid & 15;         // col group
    const int ty  = tid >> 4;         // row group
    const int m0  = blockIdx.y * 128;
    const int n0  = blockIdx.x * 128;

    // cooperative-load mapping
    const int aRow = tid >> 1;            // 0..127
    const int aCol = (tid & 1) * 4;       // 0 or 4
    const int bRow = tid >> 5;            // 0..7
    const int bCol = (tid & 31) * 4;      // 0..124

    const float* Aptr = A + (size_t)(m0 + aRow) * K + aCol;
    const float* Bptr = B + (size_t)bRow * N + (n0 + bCol);
    const bool  bValid = (n0 + bCol) < N;   // N % 4 == 0 -> all-or-nothing float4

    const int nTiles = K >> 3;

    float acc[8][8];
    #pragma unroll
    for (int i = 0; i < 8; i++)
        #pragma unroll
        for (int j = 0; j < 8; j++) acc[i][j] = 0.0f;

    // preload tile 0
    float4 aReg = *(const float4*)Aptr;
    float4 bReg = bValid ? *(const float4*)Bptr : make_float4(0.f, 0.f, 0.f, 0.f);

    As[0][aCol + 0][aRow] = aReg.x;
    As[0][aCol + 1][aRow] = aReg.y;
    As[0][aCol + 2][aRow] = aReg.z;
    As[0][aCol + 3][aRow] = aReg.w;
    *(float4*)&Bs[0][bRow][bCol] = bReg;
    __syncthreads();

    for (int kt = 0; kt < nTiles; kt++) {
        const int buf = kt & 1;

        if (kt + 1 < nTiles) {
            const int k0 = (kt + 1) * 8;
            aReg = *(const float4*)(Aptr + k0);
            bReg = bValid ? *(const float4*)(Bptr + (size_t)k0 * N)
                          : make_float4(0.f, 0.f, 0.f, 0.f);
        }

        #pragma unroll
        for (int k = 0; k < 8; k++) {
            const float4 a0 = *(const float4*)&As[buf][k][ty * 4];
            const float4 a1 = *(const float4*)&As[buf][k][64 + ty * 4];
            const float4 b0 = *(const float4*)&Bs[buf][k][tx * 4];
            const float4 b1 = *(const float4*)&Bs[buf][k][64 + tx * 4];
            const float ar[8] = {a0.x, a0.y, a0.z, a0.w, a1.x, a1.y, a1.z, a1.w};
            const float br[8] = {b0.x, b0.y, b0.z, b0.w, b1.x, b1.y, b1.z, b1.w};
            #pragma unroll
            for (int i = 0; i < 8; i++)
                #pragma unroll
                for (int j = 0; j < 8; j++)
                    acc[i][j] += ar[i] * br[j];
        }

        if (kt + 1 < nTiles) {
            const int nb = buf ^ 1;
            As[nb][aCol + 0][aRow] = aReg.x;
            As[nb][aCol + 1][aRow] = aReg.y;
            As[nb][aCol + 2][aRow] = aReg.z;
            As[nb][aCol + 3][aRow] = aReg.w;
            *(float4*)&Bs[nb][bRow][bCol] = bReg;
        }
        __syncthreads();
    }

    // epilogue: 2x2 blocks of 4x4, float4 stores
    #pragma unroll
    for (int hm = 0; hm < 2; hm++) {
        #pragma unroll
        for (int r = 0; r < 4; r++) {
            const int m = m0 + hm * 64 + ty * 4 + r;
            #pragma unroll
            for (int hn = 0; hn < 2; hn++) {
                const int n = n0 + hn * 64 + tx * 4;
                if (n < N) {
                    float4 o = make_float4(acc[hm * 4 + r][hn * 4 + 0],
                                           acc[hm * 4 + r][hn * 4 + 1],
                                           acc[hm * 4 + r][hn * 4 + 2],
                                           acc[hm * 4 + r][hn * 4 + 3]);
                    if (ADD_RESID) {
                        const float4 rv = *(const float4*)(resid + (size_t)m * N + n);
                        o.x += rv.x; o.y += rv.y; o.z += rv.z; o.w += rv.w;
                    }
                    *(float4*)(C + (size_t)m * N + n) = o;
                }
            }
        }
    }
}

// --------------- delta-rule scan: one CTA per (b, h) -----------------
__global__ void __launch_bounds__(64) scan_kernel(const float* __restrict__ qkvb,
                                                  float* __restrict__ o_out) {
    const int b   = blockIdx.x;
    const int h   = blockIdx.y;
    const int tid = threadIdx.x;
    const int lane = tid & 31, warp = tid >> 5;

    __shared__ float raws[2][200];
    __shared__ float qs[2][64], ks[2][64];
    __shared__ float red[2][2][2];

    float W[HD];
    #pragma unroll
    for (int j = 0; j < HD; j++) W[j] = 0.0f;

    const float* base = qkvb + (size_t)b * NQKVB + (size_t)h * (3 * HD + 1);
    const size_t tstride = (size_t)BSZ * NQKVB;

    float r0 = base[tid];
    float r1 = base[64 + tid];
    float r2 = base[128 + tid];
    float r3 = (tid == 0) ? base[192] : 0.0f;

    for (int t = 0; t < SLEN; t++) {
        const int par = t & 1;

        raws[par][tid]       = r0;
        raws[par][64 + tid]  = r1;
        raws[par][128 + tid] = r2;
        if (tid == 0) raws[par][192] = r3;
        __syncthreads();

        const float eq = elu_p1(r0);
        const float ek = elu_p1(r1);
        qs[par][tid] = eq;
        ks[par][tid] = ek;
        const float sq = warpsum(eq);
        const float sk = warpsum(ek);
        if (lane == 0) { red[par][0][warp] = sq; red[par][1][warp] = sk; }
        const float beta = 1.0f / (1.0f + __expf(-raws[par][192]));
        const float v_i  = r2;

        if (t + 1 < SLEN) {
            const float* p = base + (size_t)(t + 1) * tstride;
            r0 = p[tid];
            r1 = p[64 + tid];
            r2 = p[128 + tid];
            if (tid == 0) r3 = p[192];
        }
        __syncthreads();

        const float invq = 1.0f / (red[par][0][0] + red[par][0][1]);
        const float invk = 1.0f / (red[par][1][0] + red[par][1][1]);

        float a0 = 0.f, a1 = 0.f, a2 = 0.f, a3 = 0.f;
        #pragma unroll
        for (int j = 0; j < HD; j += 4) {
            const float4 k4 = *(const float4*)&ks[par][j];
            a0 += W[j]     * k4.x;
            a1 += W[j + 1] * k4.y;
            a2 += W[j + 2] * k4.z;
            a3 += W[j + 3] * k4.w;
        }
        const float vold_raw = (a0 + a1) + (a2 + a3);
        const float upd = beta * (v_i - invk * vold_raw) * invk;

        float o0 = 0.f, o1 = 0.f, o2 = 0.f, o3 = 0.f;
        #pragma unroll
        for (int j = 0; j < HD; j += 4) {
            const float4 k4 = *(const float4*)&ks[par][j];
            const float4 q4 = *(const float4*)&qs[par][j];
            W[j]     += upd * k4.x;  o0 += W[j]     * q4.x;
            W[j + 1] += upd * k4.y;  o1 += W[j + 1] * q4.y;
            W[j + 2] += upd * k4.z;  o2 += W[j + 2] * q4.z;
            W[j + 3] += upd * k4.w;  o3 += W[j + 3] * q4.w;
        }
        const float o = ((o0 + o1) + (o2 + o3)) * invq;

        o_out[((size_t)t * BSZ + b) * (NH * HD) + h * HD + tid] = o;
    }
}

// ---------------------------------------------------------------------
extern "C" void kernel_launch(void* const* d_in, const int* in_sizes, int n_in,
                              void* d_out, int out_size) {
    const float* x      = (const float*)d_in[0];
    const float* gamma  = (const float*)d_in[1];
    const float* beta   = (const float*)d_in[2];
    const float* w_slow = (const float*)d_in[3];
    const float* w_out  = (const float*)d_in[4];
    float* out = (float*)d_out;

    float *hbuf, *qkvb, *obuf;
    cudaGetSymbolAddress((void**)&hbuf, g_h);
    cudaGetSymbolAddress((void**)&qkvb, g_qkvb);
    cudaGetSymbolAddress((void**)&obuf, g_o);

    // 1) LayerNorm
    ln_kernel<<<M_ROWS, 128>>>(x, gamma, beta, hbuf);

    // 2) qkvb = h @ w_slow   [32768,512] @ [512,1544]
    sgemm128<false><<<dim3((NQKVB + 127) / 128, M_ROWS / 128), 256>>>(
        hbuf, w_slow, qkvb, nullptr, M_ROWS, NQKVB, INDIM);

    // 3) delta-rule recurrence (activations fused)
    scan_kernel<<<dim3(BSZ, NH), 64>>>(qkvb, obuf);

    // 4) out = x + o @ w_out  [32768,512] @ [512,512]
    sgemm128<true><<<dim3(INDIM / 128, M_ROWS / 128), 256>>>(
        obuf, w_out, out, x, M_ROWS, INDIM, INDIM);
}